// round 10
// baseline (speedup 1.0000x reference)
#include <cuda_runtime.h>

#define NB   16384
#define NC   64
#define NF   128
#define NT   192   // NC + NF
#define HDIM 64

// ---------------- scratch (static __device__, no allocations) ----------------
__device__ float4 g_rgbd_c[NB * NC];   // coarse rgb+density
__device__ float4 g_rgbd_f[NB * NT];   // fine rgb+density
__device__ float  g_z[NB * NT];        // merged z_vals

// ---------------- pointwise MLP kernel (1 point / thread) ----------------
template<int S, bool FINE>
__global__ __launch_bounds__(128) void mlp_kernel(
    const float* __restrict__ origins, const float* __restrict__ dirs,
    const float* __restrict__ nearp,   const float* __restrict__ farp,
    const float* __restrict__ W1, const float* __restrict__ b1,
    const float* __restrict__ W2, const float* __restrict__ b2,
    const float* __restrict__ Wr, const float* __restrict__ br,
    const float* __restrict__ Wd, const float* __restrict__ bd)
{
    __shared__ __align__(16) float sW2[HDIM * HDIM];
    __shared__ float sW1[3 * HDIM], sWr[HDIM * 3];
    __shared__ float sb1[HDIM], sb2[HDIM], sWd[HDIM];
    __shared__ float sbr[3], sbd[1];

    const int tid = threadIdx.x;
    for (int k = tid; k < HDIM * HDIM; k += 128) sW2[k] = W2[k];
    for (int k = tid; k < 3 * HDIM; k += 128) { sW1[k] = W1[k]; sWr[k] = Wr[k]; }
    if (tid < HDIM) { sb1[tid] = b1[tid]; sb2[tid] = b2[tid]; sWd[tid] = Wd[tid]; }
    if (tid < 3) sbr[tid] = br[tid];
    if (tid == 0) sbd[0] = bd[0];
    __syncthreads();

    const int idx = blockIdx.x * 128 + tid;
    const int r = idx / S;
    const int i = idx - r * S;

    float tv;
    if (FINE) {
        tv = g_z[idx];
    } else {
        float u = (float)i * (1.0f / (float)(S - 1));
        tv = nearp[r] * (1.0f - u) + farp[r] * u;
    }
    const float x0 = fmaf(tv, dirs[3 * r + 0], origins[3 * r + 0]);
    const float x1 = fmaf(tv, dirs[3 * r + 1], origins[3 * r + 1]);
    const float x2 = fmaf(tv, dirs[3 * r + 2], origins[3 * r + 2]);

    // layer 1: 3 -> 64, ReLU
    float h1v[HDIM];
#pragma unroll
    for (int j = 0; j < HDIM; j++) {
        float v = fmaf(x0, sW1[j], fmaf(x1, sW1[HDIM + j], fmaf(x2, sW1[2 * HDIM + j], sb1[j])));
        h1v[j] = fmaxf(v, 0.0f);
    }

    // layer 2: 64 -> 64 scalar FMA, fused ReLU + heads
    float ra0 = sbr[0], ra1 = sbr[1], ra2 = sbr[2], da = sbd[0];
#pragma unroll 1
    for (int c = 0; c < 2; c++) {
        float acc[32];
#pragma unroll
        for (int j = 0; j < 32; j++) acc[j] = sb2[c * 32 + j];
#pragma unroll
        for (int k = 0; k < HDIM; k++) {
            const float a = h1v[k];
            const float4* wrow = reinterpret_cast<const float4*>(sW2 + k * HDIM + c * 32);
#pragma unroll
            for (int q = 0; q < 8; q++) {
                const float4 w = wrow[q];
                acc[4 * q + 0] = fmaf(a, w.x, acc[4 * q + 0]);
                acc[4 * q + 1] = fmaf(a, w.y, acc[4 * q + 1]);
                acc[4 * q + 2] = fmaf(a, w.z, acc[4 * q + 2]);
                acc[4 * q + 3] = fmaf(a, w.w, acc[4 * q + 3]);
            }
        }
#pragma unroll
        for (int j = 0; j < 32; j++) {
            const float v = fmaxf(acc[j], 0.0f);
            const int g = c * 32 + j;
            ra0 = fmaf(v, sWr[g * 3 + 0], ra0);
            ra1 = fmaf(v, sWr[g * 3 + 1], ra1);
            ra2 = fmaf(v, sWr[g * 3 + 2], ra2);
            da  = fmaf(v, sWd[g], da);
        }
    }

    float4 o4;
    o4.x = 1.0f / (1.0f + expf(-ra0));
    o4.y = 1.0f / (1.0f + expf(-ra1));
    o4.z = 1.0f / (1.0f + expf(-ra2));
    o4.w = fmaxf(da, 0.0f);
    if (FINE) g_rgbd_f[idx] = o4; else g_rgbd_c[idx] = o4;
}

// ---------------- NAIVE coarse render + inverse-CDF resample (1 thread / ray) ----------------
__global__ __launch_bounds__(256) void render_coarse_naive(
    const float* __restrict__ origins, const float* __restrict__ dirs,
    const float* __restrict__ nearp,   const float* __restrict__ farp,
    const float* __restrict__ bkgd,    float* __restrict__ out)
{
    const int r = blockIdx.x * 256 + threadIdx.x;
    if (r >= NB) return;

    const float nr = nearp[r], fr = farp[r];
    const float dxv = dirs[3 * r], dyv = dirs[3 * r + 1], dzv = dirs[3 * r + 2];
    const float nd = sqrtf(dxv * dxv + dyv * dyv + dzv * dzv);

    // t_vals
    float t[NC];
    for (int i = 0; i < NC; i++) {
        const float u = (float)i * (1.0f / 63.0f);
        t[i] = nr * (1.0f - u) + fr * u;
    }

    // weights (serial, exactly as reference)
    float w[NC];
    {
        float run = 0.0f;
        for (int i = 0; i < NC; i++) {
            const float tdist = (i < NC - 1) ? (t[i + 1] - t[i]) : 1e10f;
            const float dd = g_rgbd_c[r * NC + i].w * (tdist * nd);
            const float alpha = 1.0f - expf(-dd);
            w[i] = alpha * expf(-run);
            run += dd;
        }
    }

    // coarse outputs
    {
        const float n0 = nearp[0], f0 = farp[0];
        float acc = 0.0f, dep = 0.0f, c0 = 0.0f, c1 = 0.0f, c2 = 0.0f, s0 = 0.0f;
        for (int i = 0; i < NC; i++) {
            const float4 rd = g_rgbd_c[r * NC + i];
            const float wi = w[i];
            acc += wi;
            dep += wi * t[i];
            c0 += wi * rd.x; c1 += wi * rd.y; c2 += wi * rd.z;
            const float u = (float)i * (1.0f / 63.0f);
            const float t0i = n0 * (1.0f - u) + f0 * u;
            s0 += wi * t0i;
        }
        float* op = out + (size_t)r * 16;
        op[0] = c0 + bkgd[0] * (1.0f - acc);
        op[1] = c1 + bkgd[1] * (1.0f - acc);
        op[2] = c2 + bkgd[2] * (1.0f - acc);
        op[3] = dep;
        op[4] = acc;
        op[5] = fmaf(dirs[0], s0, origins[0] * acc);
        op[6] = fmaf(dirs[1], s0, origins[1] * acc);
        op[7] = fmaf(dirs[2], s0, origins[2] * acc);
    }

    // bins (63) and cdf (63) over weights[1:-1] (62 values)
    float bins[NC - 1], cdf[NC - 1];
    for (int j = 0; j < NC - 1; j++) bins[j] = 0.5f * (t[j] + t[j + 1]);
    {
        float ws = 0.0f;
        for (int j = 0; j < 62; j++) ws += w[j + 1];
        const float pad  = fmaxf(1e-5f - ws, 0.0f);
        const float padd = pad * (1.0f / 62.0f);
        const float wsum = ws + pad;
        float run = 0.0f;
        cdf[0] = 0.0f;
        for (int j = 0; j < 61; j++) {
            run += (w[j + 1] + padd) / wsum;
            cdf[j + 1] = fminf(run, 1.0f);
        }
        cdf[62] = 1.0f;
    }

    // inverse-CDF sampling: 128 u's (serial linear search, exactly the reference semantics)
    float zs[NF];
    for (int s = 0; s < NF; s++) {
        const float uu = (float)s * ((1.0f - 1.1920929e-07f) / 127.0f);
        // lo = max{i in [0,62] : cdf[i] <= uu}  (cdf[0]=0 <= uu always)
        int lo = 0;
        for (int i = 1; i < 63; i++) if (cdf[i] <= uu) lo = i;
        if (lo > 61) lo = 61;   // safety (cannot trigger: cdf[62]=1 > uu)
        const float cg0 = cdf[lo], cg1 = cdf[lo + 1];
        const float bg0 = bins[lo], bg1 = bins[lo + 1];
        float den = cg1 - cg0;
        float tt = (uu - cg0) / den;
        if (!(tt == tt)) tt = 0.0f;            // nan_to_num
        tt = fminf(fmaxf(tt, 0.0f), 1.0f);
        zs[s] = fmaf(tt, bg1 - bg0, bg0);
    }

    // stable two-pointer merge: t (first) then zs, ties -> t first
    float* zr = g_z + (size_t)r * NT;
    {
        int a = 0, b = 0;
        for (int k = 0; k < NT; k++) {
            float v;
            if (b >= NF || (a < NC && t[a] <= zs[b])) v = t[a++];
            else v = zs[b++];
            zr[k] = v;
        }
    }
}

// ---------------- NAIVE fine render (1 thread / ray) ----------------
__global__ __launch_bounds__(256) void render_fine_naive(
    const float* __restrict__ origins, const float* __restrict__ dirs,
    const float* __restrict__ bkgd,    float* __restrict__ out)
{
    const int r = blockIdx.x * 256 + threadIdx.x;
    if (r >= NB) return;

    const float dxv = dirs[3 * r], dyv = dirs[3 * r + 1], dzv = dirs[3 * r + 2];
    const float nd = sqrtf(dxv * dxv + dyv * dyv + dzv * dzv);

    float z[NT];
    for (int i = 0; i < NT; i++) z[i] = g_z[(size_t)r * NT + i];

    float acc = 0.0f, dep = 0.0f, c0 = 0.0f, c1 = 0.0f, c2 = 0.0f, s0 = 0.0f;
    float run = 0.0f;
    for (int i = 0; i < NT; i++) {
        const float4 rd = g_rgbd_f[(size_t)r * NT + i];
        const float tdist = (i < NT - 1) ? (z[i + 1] - z[i]) : 1e10f;
        const float dd = rd.w * (tdist * nd);
        const float alpha = 1.0f - expf(-dd);
        const float wi = alpha * expf(-run);
        run += dd;
        acc += wi;
        dep += wi * z[i];
        c0 += wi * rd.x; c1 += wi * rd.y; c2 += wi * rd.z;
        s0 += wi * g_z[i];   // ray-0 z_vals (pts1 quirk: samples_f[0])
    }

    float* op = out + (size_t)r * 16;
    op[8]  = c0 + bkgd[0] * (1.0f - acc);
    op[9]  = c1 + bkgd[1] * (1.0f - acc);
    op[10] = c2 + bkgd[2] * (1.0f - acc);
    op[11] = dep;
    op[12] = acc;
    op[13] = fmaf(dirs[0], s0, origins[0] * acc);
    op[14] = fmaf(dirs[1], s0, origins[1] * acc);
    op[15] = fmaf(dirs[2], s0, origins[2] * acc);
}

// ---------------- launch: multi-ordering binder keyed on full size vector ----------------
extern "C" void kernel_launch(void* const* d_in, const int* in_sizes, int n_in,
                              void* d_out, int out_size)
{
    static const int csz[21] = {
        49152, 49152, 16384, 16384, 3,
        192, 64, 4096, 64, 192, 3, 64, 1,
        192, 64, 4096, 64, 192, 3, 64, 1
    };
    static const int id21[21]  = {0,1,2,3,4,5,6,7,8,9,10,11,12,13,14,15,16,17,18,19,20};
    static const int amap[21] = {
        12, 9, 11, 10, 8,
        13, 0, 15, 2, 19, 6, 17, 4,
        14, 1, 16, 3, 20, 7, 18, 5
    };
    int rsig[21], ralp[21];
    for (int k = 0; k < 21; k++) { rsig[k] = 20 - k; ralp[k] = 20 - amap[k]; }

    const int* cands[4] = { id21, amap, rsig, ralp };
    const int* perm = id21;
    if (n_in == 21) {
        for (int c = 0; c < 4; c++) {
            bool ok = true;
            for (int k = 0; k < 21; k++)
                if (in_sizes[cands[c][k]] != csz[k]) { ok = false; break; }
            if (ok) { perm = cands[c]; break; }
        }
    }

    const float* p[21];
    for (int k = 0; k < 21; k++) p[k] = (const float*)d_in[perm[k]];

    const float* origins    = p[0];
    const float* directions = p[1];
    const float* nearp      = p[2];
    const float* farp       = p[3];
    const float* bkgd       = p[4];
    const float *w1_c = p[5],  *b1_c = p[6],  *w2_c = p[7],  *b2_c = p[8];
    const float *wr_c = p[9],  *br_c = p[10], *wd_c = p[11], *bd_c = p[12];
    const float *w1_f = p[13], *b1_f = p[14], *w2_f = p[15], *b2_f = p[16];
    const float *wr_f = p[17], *br_f = p[18], *wd_f = p[19], *bd_f = p[20];
    float* out = (float*)d_out;

    mlp_kernel<NC, false><<<(NB * NC) / 128, 128>>>(
        origins, directions, nearp, farp,
        w1_c, b1_c, w2_c, b2_c, wr_c, br_c, wd_c, bd_c);

    render_coarse_naive<<<NB / 256, 256>>>(origins, directions, nearp, farp, bkgd, out);

    mlp_kernel<NT, true><<<(NB * NT) / 128, 128>>>(
        origins, directions, nearp, farp,
        w1_f, b1_f, w2_f, b2_f, wr_f, br_f, wd_f, bd_f);

    render_fine_naive<<<NB / 256, 256>>>(origins, directions, bkgd, out);
}

// round 12
// speedup vs baseline: 1.0286x; 1.0286x over previous
#include <cuda_runtime.h>

#define NB   16384
#define NC   64
#define NF   128
#define NT   192   // NC + NF
#define HDIM 64

// ---------------- scratch (static __device__, no allocations) ----------------
__device__ float4 g_rgbd_c[NB * NC];   // coarse rgb+density
__device__ float4 g_rgbd_f[NB * NT];   // fine rgb+density
__device__ float  g_z[NB * NT];        // merged z_vals

// ---------------- packed f32x2 helpers ----------------
__device__ __forceinline__ void fma2(unsigned long long &d, unsigned long long a, unsigned long long b) {
    asm("fma.rn.f32x2 %0, %1, %2, %0;" : "+l"(d) : "l"(a), "l"(b));
}
__device__ __forceinline__ unsigned long long pack2f(float lo, float hi) {
    unsigned long long r;
    asm("mov.b64 %0, {%1, %2};" : "=l"(r) : "f"(lo), "f"(hi));
    return r;
}
__device__ __forceinline__ void unpack2f(unsigned long long v, float &lo, float &hi) {
    asm("mov.b64 {%0, %1}, %2;" : "=f"(lo), "=f"(hi) : "l"(v));
}

// ---------------- pointwise MLP kernel (1 point / thread) ----------------
template<int S, bool FINE>
__global__ __launch_bounds__(128) void mlp_kernel(
    const float* __restrict__ origins, const float* __restrict__ dirs,
    const float* __restrict__ nearp,   const float* __restrict__ farp,
    const float* __restrict__ W1, const float* __restrict__ b1,
    const float* __restrict__ W2, const float* __restrict__ b2,
    const float* __restrict__ Wr, const float* __restrict__ br,
    const float* __restrict__ Wd, const float* __restrict__ bd)
{
    __shared__ __align__(16) float sW2[HDIM * HDIM];
    __shared__ float sW1[3 * HDIM], sWr[HDIM * 3];
    __shared__ float sb1[HDIM], sb2[HDIM], sWd[HDIM];
    __shared__ float sbr[3], sbd[1];

    const int tid = threadIdx.x;
    for (int k = tid; k < HDIM * HDIM; k += 128) sW2[k] = W2[k];
    for (int k = tid; k < 3 * HDIM; k += 128) { sW1[k] = W1[k]; sWr[k] = Wr[k]; }
    if (tid < HDIM) { sb1[tid] = b1[tid]; sb2[tid] = b2[tid]; sWd[tid] = Wd[tid]; }
    if (tid < 3) sbr[tid] = br[tid];
    if (tid == 0) sbd[0] = bd[0];
    __syncthreads();

    const int idx = blockIdx.x * 128 + tid;
    const int r = idx / S;
    const int i = idx - r * S;

    float tv;
    if (FINE) {
        tv = g_z[idx];
    } else {
        float u = (float)i * (1.0f / (float)(S - 1));
        tv = nearp[r] * (1.0f - u) + farp[r] * u;
    }
    const float x0 = fmaf(tv, dirs[3 * r + 0], origins[3 * r + 0]);
    const float x1 = fmaf(tv, dirs[3 * r + 1], origins[3 * r + 1]);
    const float x2 = fmaf(tv, dirs[3 * r + 2], origins[3 * r + 2]);

    // layer 1: 3 -> 64, ReLU
    float h1v[HDIM];
#pragma unroll
    for (int j = 0; j < HDIM; j++) {
        float v = fmaf(x0, sW1[j], fmaf(x1, sW1[HDIM + j], fmaf(x2, sW1[2 * HDIM + j], sb1[j])));
        h1v[j] = fmaxf(v, 0.0f);
    }

    // layer 2: 64 -> 64 (packed f32x2 FFMA2), fused ReLU + heads
    float ra0 = sbr[0], ra1 = sbr[1], ra2 = sbr[2], da = sbd[0];
#pragma unroll 1
    for (int c = 0; c < 2; c++) {
        unsigned long long acc[16];
#pragma unroll
        for (int q = 0; q < 16; q++)
            acc[q] = pack2f(sb2[c * 32 + 2 * q], sb2[c * 32 + 2 * q + 1]);
#pragma unroll
        for (int k = 0; k < HDIM; k++) {
            unsigned long long aa = pack2f(h1v[k], h1v[k]);
            const ulonglong2* wrow = reinterpret_cast<const ulonglong2*>(sW2 + k * HDIM + c * 32);
#pragma unroll
            for (int q = 0; q < 8; q++) {
                ulonglong2 wv = wrow[q];
                fma2(acc[2 * q],     aa, wv.x);
                fma2(acc[2 * q + 1], aa, wv.y);
            }
        }
#pragma unroll
        for (int q = 0; q < 16; q++) {
            float v0, v1;
            unpack2f(acc[q], v0, v1);
            v0 = fmaxf(v0, 0.0f);
            v1 = fmaxf(v1, 0.0f);
            const int g0 = c * 32 + 2 * q;
            ra0 = fmaf(v0, sWr[g0 * 3 + 0], ra0); ra0 = fmaf(v1, sWr[g0 * 3 + 3], ra0);
            ra1 = fmaf(v0, sWr[g0 * 3 + 1], ra1); ra1 = fmaf(v1, sWr[g0 * 3 + 4], ra1);
            ra2 = fmaf(v0, sWr[g0 * 3 + 2], ra2); ra2 = fmaf(v1, sWr[g0 * 3 + 5], ra2);
            da  = fmaf(v0, sWd[g0],     da);
            da  = fmaf(v1, sWd[g0 + 1], da);
        }
    }

    float4 o4;
    o4.x = 1.0f / (1.0f + expf(-ra0));
    o4.y = 1.0f / (1.0f + expf(-ra1));
    o4.z = 1.0f / (1.0f + expf(-ra2));
    o4.w = fmaxf(da, 0.0f);
    if (FINE) g_rgbd_f[idx] = o4; else g_rgbd_c[idx] = o4;
}

// ---------------- NAIVE coarse render + inverse-CDF resample (1 thread / ray) ----------------
__global__ __launch_bounds__(256) void render_coarse_naive(
    const float* __restrict__ origins, const float* __restrict__ dirs,
    const float* __restrict__ nearp,   const float* __restrict__ farp,
    const float* __restrict__ bkgd,    float* __restrict__ out)
{
    const int r = blockIdx.x * 256 + threadIdx.x;
    if (r >= NB) return;

    const float nr = nearp[r], fr = farp[r];
    const float dxv = dirs[3 * r], dyv = dirs[3 * r + 1], dzv = dirs[3 * r + 2];
    const float nd = sqrtf(dxv * dxv + dyv * dyv + dzv * dzv);

    // t_vals
    float t[NC];
    for (int i = 0; i < NC; i++) {
        const float u = (float)i * (1.0f / 63.0f);
        t[i] = nr * (1.0f - u) + fr * u;
    }

    // weights (serial, exactly as reference)
    float w[NC];
    {
        float run = 0.0f;
        for (int i = 0; i < NC; i++) {
            const float tdist = (i < NC - 1) ? (t[i + 1] - t[i]) : 1e10f;
            const float dd = g_rgbd_c[r * NC + i].w * (tdist * nd);
            const float alpha = 1.0f - expf(-dd);
            w[i] = alpha * expf(-run);
            run += dd;
        }
    }

    // coarse outputs
    {
        const float n0 = nearp[0], f0 = farp[0];
        float acc = 0.0f, dep = 0.0f, c0 = 0.0f, c1 = 0.0f, c2 = 0.0f, s0 = 0.0f;
        for (int i = 0; i < NC; i++) {
            const float4 rd = g_rgbd_c[r * NC + i];
            const float wi = w[i];
            acc += wi;
            dep += wi * t[i];
            c0 += wi * rd.x; c1 += wi * rd.y; c2 += wi * rd.z;
            const float u = (float)i * (1.0f / 63.0f);
            const float t0i = n0 * (1.0f - u) + f0 * u;
            s0 += wi * t0i;
        }
        float* op = out + (size_t)r * 16;
        op[0] = c0 + bkgd[0] * (1.0f - acc);
        op[1] = c1 + bkgd[1] * (1.0f - acc);
        op[2] = c2 + bkgd[2] * (1.0f - acc);
        op[3] = dep;
        op[4] = acc;
        op[5] = fmaf(dirs[0], s0, origins[0] * acc);
        op[6] = fmaf(dirs[1], s0, origins[1] * acc);
        op[7] = fmaf(dirs[2], s0, origins[2] * acc);
    }

    // bins (63) and cdf (63) over weights[1:-1] (62 values)
    float bins[NC - 1], cdf[NC - 1];
    for (int j = 0; j < NC - 1; j++) bins[j] = 0.5f * (t[j] + t[j + 1]);
    {
        float ws = 0.0f;
        for (int j = 0; j < 62; j++) ws += w[j + 1];
        const float pad  = fmaxf(1e-5f - ws, 0.0f);
        const float padd = pad * (1.0f / 62.0f);
        const float wsum = ws + pad;
        float run = 0.0f;
        cdf[0] = 0.0f;
        for (int j = 0; j < 61; j++) {
            run += (w[j + 1] + padd) / wsum;
            cdf[j + 1] = fminf(run, 1.0f);
        }
        cdf[62] = 1.0f;
    }

    // inverse-CDF sampling: 128 u's (serial linear search, exactly the reference semantics)
    float zs[NF];
    for (int s = 0; s < NF; s++) {
        const float uu = (float)s * ((1.0f - 1.1920929e-07f) / 127.0f);
        int lo = 0;
        for (int i = 1; i < 63; i++) if (cdf[i] <= uu) lo = i;
        if (lo > 61) lo = 61;   // safety (cannot trigger: cdf[62]=1 > uu)
        const float cg0 = cdf[lo], cg1 = cdf[lo + 1];
        const float bg0 = bins[lo], bg1 = bins[lo + 1];
        float den = cg1 - cg0;
        float tt = (uu - cg0) / den;
        if (!(tt == tt)) tt = 0.0f;            // nan_to_num
        tt = fminf(fmaxf(tt, 0.0f), 1.0f);
        zs[s] = fmaf(tt, bg1 - bg0, bg0);
    }

    // stable two-pointer merge: t (first) then zs, ties -> t first
    float* zr = g_z + (size_t)r * NT;
    {
        int a = 0, b = 0;
        for (int k = 0; k < NT; k++) {
            float v;
            if (b >= NF || (a < NC && t[a] <= zs[b])) v = t[a++];
            else v = zs[b++];
            zr[k] = v;
        }
    }
}

// ---------------- NAIVE fine render (1 thread / ray) ----------------
__global__ __launch_bounds__(256) void render_fine_naive(
    const float* __restrict__ origins, const float* __restrict__ dirs,
    const float* __restrict__ bkgd,    float* __restrict__ out)
{
    const int r = blockIdx.x * 256 + threadIdx.x;
    if (r >= NB) return;

    const float dxv = dirs[3 * r], dyv = dirs[3 * r + 1], dzv = dirs[3 * r + 2];
    const float nd = sqrtf(dxv * dxv + dyv * dyv + dzv * dzv);

    float z[NT];
    for (int i = 0; i < NT; i++) z[i] = g_z[(size_t)r * NT + i];

    float acc = 0.0f, dep = 0.0f, c0 = 0.0f, c1 = 0.0f, c2 = 0.0f, s0 = 0.0f;
    float run = 0.0f;
    for (int i = 0; i < NT; i++) {
        const float4 rd = g_rgbd_f[(size_t)r * NT + i];
        const float tdist = (i < NT - 1) ? (z[i + 1] - z[i]) : 1e10f;
        const float dd = rd.w * (tdist * nd);
        const float alpha = 1.0f - expf(-dd);
        const float wi = alpha * expf(-run);
        run += dd;
        acc += wi;
        dep += wi * z[i];
        c0 += wi * rd.x; c1 += wi * rd.y; c2 += wi * rd.z;
        s0 += wi * g_z[i];   // ray-0 z_vals (pts1 quirk: samples_f[0])
    }

    float* op = out + (size_t)r * 16;
    op[8]  = c0 + bkgd[0] * (1.0f - acc);
    op[9]  = c1 + bkgd[1] * (1.0f - acc);
    op[10] = c2 + bkgd[2] * (1.0f - acc);
    op[11] = dep;
    op[12] = acc;
    op[13] = fmaf(dirs[0], s0, origins[0] * acc);
    op[14] = fmaf(dirs[1], s0, origins[1] * acc);
    op[15] = fmaf(dirs[2], s0, origins[2] * acc);
}

// ---------------- launch: multi-ordering binder keyed on full size vector ----------------
extern "C" void kernel_launch(void* const* d_in, const int* in_sizes, int n_in,
                              void* d_out, int out_size)
{
    static const int csz[21] = {
        49152, 49152, 16384, 16384, 3,
        192, 64, 4096, 64, 192, 3, 64, 1,
        192, 64, 4096, 64, 192, 3, 64, 1
    };
    static const int id21[21]  = {0,1,2,3,4,5,6,7,8,9,10,11,12,13,14,15,16,17,18,19,20};
    static const int amap[21] = {
        12, 9, 11, 10, 8,
        13, 0, 15, 2, 19, 6, 17, 4,
        14, 1, 16, 3, 20, 7, 18, 5
    };
    int rsig[21], ralp[21];
    for (int k = 0; k < 21; k++) { rsig[k] = 20 - k; ralp[k] = 20 - amap[k]; }

    const int* cands[4] = { id21, amap, rsig, ralp };
    const int* perm = id21;
    if (n_in == 21) {
        for (int c = 0; c < 4; c++) {
            bool ok = true;
            for (int k = 0; k < 21; k++)
                if (in_sizes[cands[c][k]] != csz[k]) { ok = false; break; }
            if (ok) { perm = cands[c]; break; }
        }
    }

    const float* p[21];
    for (int k = 0; k < 21; k++) p[k] = (const float*)d_in[perm[k]];

    const float* origins    = p[0];
    const float* directions = p[1];
    const float* nearp      = p[2];
    const float* farp       = p[3];
    const float* bkgd       = p[4];
    const float *w1_c = p[5],  *b1_c = p[6],  *w2_c = p[7],  *b2_c = p[8];
    const float *wr_c = p[9],  *br_c = p[10], *wd_c = p[11], *bd_c = p[12];
    const float *w1_f = p[13], *b1_f = p[14], *w2_f = p[15], *b2_f = p[16];
    const float *wr_f = p[17], *br_f = p[18], *wd_f = p[19], *bd_f = p[20];
    float* out = (float*)d_out;

    mlp_kernel<NC, false><<<(NB * NC) / 128, 128>>>(
        origins, directions, nearp, farp,
        w1_c, b1_c, w2_c, b2_c, wr_c, br_c, wd_c, bd_c);

    render_coarse_naive<<<NB / 256, 256>>>(origins, directions, nearp, farp, bkgd, out);

    mlp_kernel<NT, true><<<(NB * NT) / 128, 128>>>(
        origins, directions, nearp, farp,
        w1_f, b1_f, w2_f, b2_f, wr_f, br_f, wd_f, bd_f);

    render_fine_naive<<<NB / 256, 256>>>(origins, directions, bkgd, out);
}

// round 13
// speedup vs baseline: 1.0654x; 1.0358x over previous
#include <cuda_runtime.h>

#define NB   16384
#define NC   64
#define NF   128
#define NT   192   // NC + NF
#define HDIM 64

// ---------------- scratch (static __device__, no allocations) ----------------
__device__ float4 g_rgbd_c[NB * NC];   // coarse rgb+density
__device__ float4 g_rgbd_f[NB * NT];   // fine rgb+density
__device__ float  g_z[NB * NT];        // merged z_vals

// ---------------- packed f32x2 helpers ----------------
__device__ __forceinline__ void fma2(unsigned long long &d, unsigned long long a, unsigned long long b) {
    asm("fma.rn.f32x2 %0, %1, %2, %0;" : "+l"(d) : "l"(a), "l"(b));
}
__device__ __forceinline__ unsigned long long pack2f(float lo, float hi) {
    unsigned long long r;
    asm("mov.b64 %0, {%1, %2};" : "=l"(r) : "f"(lo), "f"(hi));
    return r;
}
__device__ __forceinline__ void unpack2f(unsigned long long v, float &lo, float &hi) {
    asm("mov.b64 {%0, %1}, %2;" : "=f"(lo), "=f"(hi) : "l"(v));
}

// ---------------- pointwise MLP kernel (1 point / thread) ----------------
template<int S, bool FINE>
__global__ __launch_bounds__(128) void mlp_kernel(
    const float* __restrict__ origins, const float* __restrict__ dirs,
    const float* __restrict__ nearp,   const float* __restrict__ farp,
    const float* __restrict__ W1, const float* __restrict__ b1,
    const float* __restrict__ W2, const float* __restrict__ b2,
    const float* __restrict__ Wr, const float* __restrict__ br,
    const float* __restrict__ Wd, const float* __restrict__ bd)
{
    __shared__ __align__(16) float sW2[HDIM * HDIM];
    __shared__ float sW1[3 * HDIM], sWr[HDIM * 3];
    __shared__ float sb1[HDIM], sb2[HDIM], sWd[HDIM];
    __shared__ float sbr[3], sbd[1];

    const int tid = threadIdx.x;
    for (int k = tid; k < HDIM * HDIM; k += 128) sW2[k] = W2[k];
    for (int k = tid; k < 3 * HDIM; k += 128) { sW1[k] = W1[k]; sWr[k] = Wr[k]; }
    if (tid < HDIM) { sb1[tid] = b1[tid]; sb2[tid] = b2[tid]; sWd[tid] = Wd[tid]; }
    if (tid < 3) sbr[tid] = br[tid];
    if (tid == 0) sbd[0] = bd[0];
    __syncthreads();

    const int idx = blockIdx.x * 128 + tid;
    const int r = idx / S;
    const int i = idx - r * S;

    float tv;
    if (FINE) {
        tv = g_z[idx];
    } else {
        float u = (float)i * (1.0f / (float)(S - 1));
        tv = nearp[r] * (1.0f - u) + farp[r] * u;
    }
    const float x0 = fmaf(tv, dirs[3 * r + 0], origins[3 * r + 0]);
    const float x1 = fmaf(tv, dirs[3 * r + 1], origins[3 * r + 1]);
    const float x2 = fmaf(tv, dirs[3 * r + 2], origins[3 * r + 2]);

    // layer 1: 3 -> 64, ReLU
    float h1v[HDIM];
#pragma unroll
    for (int j = 0; j < HDIM; j++) {
        float v = fmaf(x0, sW1[j], fmaf(x1, sW1[HDIM + j], fmaf(x2, sW1[2 * HDIM + j], sb1[j])));
        h1v[j] = fmaxf(v, 0.0f);
    }

    // layer 2: 64 -> 64 (packed f32x2 FFMA2), fused ReLU + heads
    float ra0 = sbr[0], ra1 = sbr[1], ra2 = sbr[2], da = sbd[0];
#pragma unroll 1
    for (int c = 0; c < 2; c++) {
        unsigned long long acc[16];
#pragma unroll
        for (int q = 0; q < 16; q++)
            acc[q] = pack2f(sb2[c * 32 + 2 * q], sb2[c * 32 + 2 * q + 1]);
#pragma unroll
        for (int k = 0; k < HDIM; k++) {
            unsigned long long aa = pack2f(h1v[k], h1v[k]);
            const ulonglong2* wrow = reinterpret_cast<const ulonglong2*>(sW2 + k * HDIM + c * 32);
#pragma unroll
            for (int q = 0; q < 8; q++) {
                ulonglong2 wv = wrow[q];
                fma2(acc[2 * q],     aa, wv.x);
                fma2(acc[2 * q + 1], aa, wv.y);
            }
        }
#pragma unroll
        for (int q = 0; q < 16; q++) {
            float v0, v1;
            unpack2f(acc[q], v0, v1);
            v0 = fmaxf(v0, 0.0f);
            v1 = fmaxf(v1, 0.0f);
            const int g0 = c * 32 + 2 * q;
            ra0 = fmaf(v0, sWr[g0 * 3 + 0], ra0); ra0 = fmaf(v1, sWr[g0 * 3 + 3], ra0);
            ra1 = fmaf(v0, sWr[g0 * 3 + 1], ra1); ra1 = fmaf(v1, sWr[g0 * 3 + 4], ra1);
            ra2 = fmaf(v0, sWr[g0 * 3 + 2], ra2); ra2 = fmaf(v1, sWr[g0 * 3 + 5], ra2);
            da  = fmaf(v0, sWd[g0],     da);
            da  = fmaf(v1, sWd[g0 + 1], da);
        }
    }

    float4 o4;
    o4.x = 1.0f / (1.0f + expf(-ra0));
    o4.y = 1.0f / (1.0f + expf(-ra1));
    o4.z = 1.0f / (1.0f + expf(-ra2));
    o4.w = fmaxf(da, 0.0f);
    if (FINE) g_rgbd_f[idx] = o4; else g_rgbd_c[idx] = o4;
}

// ---------------- NAIVE coarse render + inverse-CDF resample (1 thread / ray) ----------------
__global__ __launch_bounds__(64) void render_coarse_naive(
    const float* __restrict__ origins, const float* __restrict__ dirs,
    const float* __restrict__ nearp,   const float* __restrict__ farp,
    const float* __restrict__ bkgd,    float* __restrict__ out)
{
    const int r = blockIdx.x * 64 + threadIdx.x;
    if (r >= NB) return;

    const float nr = nearp[r], fr = farp[r];
    const float dxv = dirs[3 * r], dyv = dirs[3 * r + 1], dzv = dirs[3 * r + 2];
    const float nd = sqrtf(dxv * dxv + dyv * dyv + dzv * dzv);

    // t_vals
    float t[NC];
    for (int i = 0; i < NC; i++) {
        const float u = (float)i * (1.0f / 63.0f);
        t[i] = nr * (1.0f - u) + fr * u;
    }

    // weights (serial, exactly as reference)
    float w[NC];
    {
        float run = 0.0f;
        for (int i = 0; i < NC; i++) {
            const float tdist = (i < NC - 1) ? (t[i + 1] - t[i]) : 1e10f;
            const float dd = g_rgbd_c[r * NC + i].w * (tdist * nd);
            const float alpha = 1.0f - expf(-dd);
            w[i] = alpha * expf(-run);
            run += dd;
        }
    }

    // coarse outputs
    {
        const float n0 = nearp[0], f0 = farp[0];
        float acc = 0.0f, dep = 0.0f, c0 = 0.0f, c1 = 0.0f, c2 = 0.0f, s0 = 0.0f;
        for (int i = 0; i < NC; i++) {
            const float4 rd = g_rgbd_c[r * NC + i];
            const float wi = w[i];
            acc += wi;
            dep += wi * t[i];
            c0 += wi * rd.x; c1 += wi * rd.y; c2 += wi * rd.z;
            const float u = (float)i * (1.0f / 63.0f);
            const float t0i = n0 * (1.0f - u) + f0 * u;
            s0 += wi * t0i;
        }
        float* op = out + (size_t)r * 16;
        op[0] = c0 + bkgd[0] * (1.0f - acc);
        op[1] = c1 + bkgd[1] * (1.0f - acc);
        op[2] = c2 + bkgd[2] * (1.0f - acc);
        op[3] = dep;
        op[4] = acc;
        op[5] = fmaf(dirs[0], s0, origins[0] * acc);
        op[6] = fmaf(dirs[1], s0, origins[1] * acc);
        op[7] = fmaf(dirs[2], s0, origins[2] * acc);
    }

    // bins (63) and cdf (63) over weights[1:-1] (62 values)
    float bins[NC - 1], cdf[NC - 1];
    for (int j = 0; j < NC - 1; j++) bins[j] = 0.5f * (t[j] + t[j + 1]);
    {
        float ws = 0.0f;
        for (int j = 0; j < 62; j++) ws += w[j + 1];
        const float pad  = fmaxf(1e-5f - ws, 0.0f);
        const float padd = pad * (1.0f / 62.0f);
        const float wsum = ws + pad;
        float run = 0.0f;
        cdf[0] = 0.0f;
        for (int j = 0; j < 61; j++) {
            run += (w[j + 1] + padd) / wsum;
            cdf[j + 1] = fminf(run, 1.0f);
        }
        cdf[62] = 1.0f;
    }

    // inverse-CDF sampling: 128 ascending u's.
    // lo(s) = max{i in [0,62] : cdf[i] <= u_s} is monotone non-decreasing in s,
    // so a two-pointer sweep visits each cdf entry once (same result as full search).
    float zs[NF];
    {
        int lo = 0;
        for (int s = 0; s < NF; s++) {
            const float uu = (float)s * ((1.0f - 1.1920929e-07f) / 127.0f);
            while (lo + 1 <= 62 && cdf[lo + 1] <= uu) lo++;
            int l = (lo > 61) ? 61 : lo;
            const float cg0 = cdf[l], cg1 = cdf[l + 1];
            const float bg0 = bins[l], bg1 = bins[l + 1];
            float tt = (uu - cg0) / (cg1 - cg0);
            if (!(tt == tt)) tt = 0.0f;            // nan_to_num
            tt = fminf(fmaxf(tt, 0.0f), 1.0f);
            zs[s] = fmaf(tt, bg1 - bg0, bg0);
        }
    }

    // stable two-pointer merge: t (first) then zs, ties -> t first
    float* zr = g_z + (size_t)r * NT;
    {
        int a = 0, b = 0;
        for (int k = 0; k < NT; k++) {
            float v;
            if (b >= NF || (a < NC && t[a] <= zs[b])) v = t[a++];
            else v = zs[b++];
            zr[k] = v;
        }
    }
}

// ---------------- NAIVE fine render (1 thread / ray) ----------------
__global__ __launch_bounds__(64) void render_fine_naive(
    const float* __restrict__ origins, const float* __restrict__ dirs,
    const float* __restrict__ bkgd,    float* __restrict__ out)
{
    const int r = blockIdx.x * 64 + threadIdx.x;
    if (r >= NB) return;

    const float dxv = dirs[3 * r], dyv = dirs[3 * r + 1], dzv = dirs[3 * r + 2];
    const float nd = sqrtf(dxv * dxv + dyv * dyv + dzv * dzv);

    float z[NT];
    for (int i = 0; i < NT; i++) z[i] = g_z[(size_t)r * NT + i];

    float acc = 0.0f, dep = 0.0f, c0 = 0.0f, c1 = 0.0f, c2 = 0.0f, s0 = 0.0f;
    float run = 0.0f;
    for (int i = 0; i < NT; i++) {
        const float4 rd = g_rgbd_f[(size_t)r * NT + i];
        const float tdist = (i < NT - 1) ? (z[i + 1] - z[i]) : 1e10f;
        const float dd = rd.w * (tdist * nd);
        const float alpha = 1.0f - expf(-dd);
        const float wi = alpha * expf(-run);
        run += dd;
        acc += wi;
        dep += wi * z[i];
        c0 += wi * rd.x; c1 += wi * rd.y; c2 += wi * rd.z;
        s0 += wi * g_z[i];   // ray-0 z_vals (pts1 quirk: samples_f[0])
    }

    float* op = out + (size_t)r * 16;
    op[8]  = c0 + bkgd[0] * (1.0f - acc);
    op[9]  = c1 + bkgd[1] * (1.0f - acc);
    op[10] = c2 + bkgd[2] * (1.0f - acc);
    op[11] = dep;
    op[12] = acc;
    op[13] = fmaf(dirs[0], s0, origins[0] * acc);
    op[14] = fmaf(dirs[1], s0, origins[1] * acc);
    op[15] = fmaf(dirs[2], s0, origins[2] * acc);
}

// ---------------- launch: multi-ordering binder keyed on full size vector ----------------
extern "C" void kernel_launch(void* const* d_in, const int* in_sizes, int n_in,
                              void* d_out, int out_size)
{
    static const int csz[21] = {
        49152, 49152, 16384, 16384, 3,
        192, 64, 4096, 64, 192, 3, 64, 1,
        192, 64, 4096, 64, 192, 3, 64, 1
    };
    static const int id21[21]  = {0,1,2,3,4,5,6,7,8,9,10,11,12,13,14,15,16,17,18,19,20};
    static const int amap[21] = {
        12, 9, 11, 10, 8,
        13, 0, 15, 2, 19, 6, 17, 4,
        14, 1, 16, 3, 20, 7, 18, 5
    };
    int rsig[21], ralp[21];
    for (int k = 0; k < 21; k++) { rsig[k] = 20 - k; ralp[k] = 20 - amap[k]; }

    const int* cands[4] = { id21, amap, rsig, ralp };
    const int* perm = id21;
    if (n_in == 21) {
        for (int c = 0; c < 4; c++) {
            bool ok = true;
            for (int k = 0; k < 21; k++)
                if (in_sizes[cands[c][k]] != csz[k]) { ok = false; break; }
            if (ok) { perm = cands[c]; break; }
        }
    }

    const float* p[21];
    for (int k = 0; k < 21; k++) p[k] = (const float*)d_in[perm[k]];

    const float* origins    = p[0];
    const float* directions = p[1];
    const float* nearp      = p[2];
    const float* farp       = p[3];
    const float* bkgd       = p[4];
    const float *w1_c = p[5],  *b1_c = p[6],  *w2_c = p[7],  *b2_c = p[8];
    const float *wr_c = p[9],  *br_c = p[10], *wd_c = p[11], *bd_c = p[12];
    const float *w1_f = p[13], *b1_f = p[14], *w2_f = p[15], *b2_f = p[16];
    const float *wr_f = p[17], *br_f = p[18], *wd_f = p[19], *bd_f = p[20];
    float* out = (float*)d_out;

    mlp_kernel<NC, false><<<(NB * NC) / 128, 128>>>(
        origins, directions, nearp, farp,
        w1_c, b1_c, w2_c, b2_c, wr_c, br_c, wd_c, bd_c);

    render_coarse_naive<<<NB / 64, 64>>>(origins, directions, nearp, farp, bkgd, out);

    mlp_kernel<NT, true><<<(NB * NT) / 128, 128>>>(
        origins, directions, nearp, farp,
        w1_f, b1_f, w2_f, b2_f, wr_f, br_f, wd_f, bd_f);

    render_fine_naive<<<NB / 64, 64>>>(origins, directions, bkgd, out);
}